// round 9
// baseline (speedup 1.0000x reference)
#include <cuda_runtime.h>

#define BQ 4096
#define TT 200
#define DD 64
#define HH 64

// ---------------- scratch (static device globals: allocation-free) ----------
__device__ int g_hist[256];
__device__ int g_cursor[256];
__device__ int g_perm[BQ];
__device__ int g_qhead;

// ---------------- counting sort of rows by seq_len --------------------------
__global__ void k_hist_init() {
    int i = threadIdx.x;
    g_hist[i] = 0;
    if (i == 0) g_qhead = 0;
}

__global__ void k_hist(const int* __restrict__ sl) {
    int i = blockIdx.x * blockDim.x + threadIdx.x;
    if (i < BQ) atomicAdd(&g_hist[sl[i] & 255], 1);
}

__global__ void k_scan() {
    if (threadIdx.x == 0) {
        int s = 0;
        for (int i = 0; i < 256; i++) { int c = g_hist[i]; g_cursor[i] = s; s += c; }
    }
}

__global__ void k_scatter(const int* __restrict__ sl) {
    int i = blockIdx.x * blockDim.x + threadIdx.x;
    if (i < BQ) {
        int pos = atomicAdd(&g_cursor[sl[i] & 255], 1);
        g_perm[pos] = i;
    }
}

// ---------------- math helpers ----------------------------------------------
__device__ __forceinline__ float sigf(float v) {
    return __fdividef(1.f, 1.f + __expf(-v));
}

// ---------------- main AUGRU kernel -----------------------------------------
// One warp owns one row (sequence) at a time, pulled from a descending-L queue.
// SMEM: Wg transposed to [k][lane*4+c] (c in {0,1,2,3} -> output lane+32c),
//       Wc transposed to [k][lane*2+c] (c in {0,1}   -> output lane+32c),
//       per-warp 192-float staging buffer: [0:64)=x_t, [64:128)=h, [128:192)=r*h.
__global__ void __launch_bounds__(256, 1)
augru_main(const float* __restrict__ x, const int* __restrict__ sl,
           const float* __restrict__ att, const float* __restrict__ Wg,
           const float* __restrict__ bg, const float* __restrict__ Wc,
           const float* __restrict__ bc, float* __restrict__ out)
{
    extern __shared__ float sm[];
    float* sWg  = sm;               // 16384 floats
    float* sWc  = sm + 16384;       // 8192 floats
    float* sBg  = sm + 24576;       // 128
    float* sBc  = sm + 24704;       // 64
    float* sBuf = sm + 24768;       // 8 warps * 192

    const int tid = threadIdx.x;

    // cooperative weight load, transposed for per-lane vector LDS
    for (int i = tid; i < 128 * 128; i += 256) {
        int k = i >> 7, j = i & 127;                 // j = lane*4 + c
        sWg[i] = Wg[k * 128 + ((j & 3) << 5) + (j >> 2)];
    }
    for (int i = tid; i < 128 * 64; i += 256) {
        int k = i >> 6, j = i & 63;                  // j = lane*2 + c
        sWc[i] = Wc[k * 64 + ((j & 1) << 5) + (j >> 1)];
    }
    if (tid < 128) sBg[tid] = bg[tid];
    if (tid < 64)  sBc[tid] = bc[tid];
    __syncthreads();

    const int lane = tid & 31;
    float* rb = sBuf + (tid >> 5) * 192;

    const float bgv0 = sBg[lane], bgv1 = sBg[lane + 32];
    const float bgv2 = sBg[lane + 64], bgv3 = sBg[lane + 96];
    const float bcv0 = sBc[lane], bcv1 = sBc[lane + 32];

    for (;;) {
        int ci = 0;
        if (lane == 0) ci = atomicAdd(&g_qhead, 1);
        ci = __shfl_sync(0xffffffffu, ci, 0);
        if (ci >= BQ) break;

        const int row = g_perm[BQ - 1 - ci];         // descending L order
        const int L = sl[row];
        const float* xb = x + (size_t)row * TT * DD;
        const float* ab = att + (size_t)row * TT;
        float* ob = out + (size_t)row * TT * HH;

        float h0 = 0.f, h1 = 0.f;
        rb[64 + lane] = 0.f; rb[96 + lane] = 0.f;

        float px0 = 0.f, px1 = 0.f, pa = 0.f;
        if (L > 0) { px0 = xb[lane]; px1 = xb[lane + 32]; pa = ab[0]; }

        for (int t = 0; t < L; t++) {
            __syncwarp();                            // protect prev-iter reads / h writes
            rb[lane] = px0; rb[32 + lane] = px1;
            const float at_s = pa;
            __syncwarp();                            // x/h visible to all lanes

            // prefetch next timestep while matvecs run
            {
                const int tn = t + 1;
                if (tn < L) {
                    const float* xp = xb + tn * DD;
                    px0 = xp[lane]; px1 = xp[lane + 32]; pa = ab[tn];
                }
            }

            // ---- gate matvec: [x;h](128) @ Wg(128x128) ----
            float a0 = bgv0, a1 = bgv1, a2 = bgv2, a3 = bgv3;
            #pragma unroll 4
            for (int k4 = 0; k4 < 128; k4 += 4) {
                const float4 bv = *(const float4*)(rb + k4);
                const float* wp = sWg + k4 * 128 + lane * 4;
                float4 w0 = *(const float4*)(wp);
                float4 w1 = *(const float4*)(wp + 128);
                float4 w2 = *(const float4*)(wp + 256);
                float4 w3 = *(const float4*)(wp + 384);
                a0 += w0.x * bv.x; a1 += w0.y * bv.x; a2 += w0.z * bv.x; a3 += w0.w * bv.x;
                a0 += w1.x * bv.y; a1 += w1.y * bv.y; a2 += w1.z * bv.y; a3 += w1.w * bv.y;
                a0 += w2.x * bv.z; a1 += w2.y * bv.z; a2 += w2.z * bv.z; a3 += w2.w * bv.z;
                a0 += w3.x * bv.w; a1 += w3.y * bv.w; a2 += w3.z * bv.w; a3 += w3.w * bv.w;
            }
            const float r0 = sigf(a0), r1 = sigf(a1);
            const float u0 = sigf(a2), u1 = sigf(a3);
            rb[128 + lane] = r0 * h0;
            rb[160 + lane] = r1 * h1;
            __syncwarp();                            // r*h visible

            // ---- candidate matvec: [x; r*h](128) @ Wc(128x64) ----
            float c0 = bcv0, c1 = bcv1;
            #pragma unroll 4
            for (int k4 = 0; k4 < 64; k4 += 4) {
                const float4 bv = *(const float4*)(rb + k4);          // x part
                const float* wp = sWc + k4 * 64 + lane * 2;
                float2 w0 = *(const float2*)(wp);
                float2 w1 = *(const float2*)(wp + 64);
                float2 w2 = *(const float2*)(wp + 128);
                float2 w3 = *(const float2*)(wp + 192);
                c0 += w0.x * bv.x; c1 += w0.y * bv.x;
                c0 += w1.x * bv.y; c1 += w1.y * bv.y;
                c0 += w2.x * bv.z; c1 += w2.y * bv.z;
                c0 += w3.x * bv.w; c1 += w3.y * bv.w;
            }
            #pragma unroll 4
            for (int k4 = 0; k4 < 64; k4 += 4) {
                const float4 bv = *(const float4*)(rb + 128 + k4);    // r*h part
                const float* wp = sWc + (64 + k4) * 64 + lane * 2;
                float2 w0 = *(const float2*)(wp);
                float2 w1 = *(const float2*)(wp + 64);
                float2 w2 = *(const float2*)(wp + 128);
                float2 w3 = *(const float2*)(wp + 192);
                c0 += w0.x * bv.x; c1 += w0.y * bv.x;
                c0 += w1.x * bv.y; c1 += w1.y * bv.y;
                c0 += w2.x * bv.z; c1 += w2.y * bv.z;
                c0 += w3.x * bv.w; c1 += w3.y * bv.w;
            }
            const float ct0 = tanhf(c0), ct1 = tanhf(c1);

            const float uu0 = (1.f - at_s) * u0;
            const float uu1 = (1.f - at_s) * u1;
            h0 = uu0 * h0 + (1.f - uu0) * ct0;
            h1 = uu1 * h1 + (1.f - uu1) * ct1;

            float* op = ob + t * HH;
            op[lane] = h0; op[lane + 32] = h1;
            rb[64 + lane] = h0; rb[96 + lane] = h1;  // stage h for next step
        }

        // zero-fill masked tail (output poisoned by harness)
        float* op = ob + L * HH;
        for (int t = L; t < TT; t++) {
            op[lane] = 0.f; op[lane + 32] = 0.f;
            op += HH;
        }
    }
}

// ---------------- launch -----------------------------------------------------
extern "C" void kernel_launch(void* const* d_in, const int* in_sizes, int n_in,
                              void* d_out, int out_size)
{
    const float* x  = (const float*)d_in[0];   // rnn_input  [B,T,64]
    const int*   sl = (const int*)d_in[1];     // sequence_length [B,1]
    const float* at = (const float*)d_in[2];   // att_score  [B,T,1]
    const float* Wg = (const float*)d_in[3];   // [128,128]
    const float* bg = (const float*)d_in[4];   // [128]
    const float* Wc = (const float*)d_in[5];   // [128,64]
    const float* bc = (const float*)d_in[6];   // [64]
    float* out = (float*)d_out;                // [B,T,64]

    const int smem_bytes = (16384 + 8192 + 128 + 64 + 8 * 192) * 4; // 105216
    cudaFuncSetAttribute(augru_main, cudaFuncAttributeMaxDynamicSharedMemorySize,
                         smem_bytes);

    k_hist_init<<<1, 256>>>();
    k_hist<<<(BQ + 255) / 256, 256>>>(sl);
    k_scan<<<1, 32>>>();
    k_scatter<<<(BQ + 255) / 256, 256>>>(sl);
    augru_main<<<148, 256, smem_bytes>>>(x, sl, at, Wg, bg, Wc, bc, out);
}

// round 10
// speedup vs baseline: 1.0001x; 1.0001x over previous
#include <cuda_runtime.h>

#define BQ 4096
#define TT 200
#define DD 64
#define HH 64

// ---------------- scratch (static device globals: allocation-free) ----------
__device__ int g_hist[256];
__device__ int g_cursor[256];
__device__ int g_perm[BQ];
__device__ int g_qhead;

// ---------------- counting sort of rows by seq_len --------------------------
__global__ void k_hist_init() {
    int i = threadIdx.x;
    g_hist[i] = 0;
    if (i == 0) g_qhead = 0;
}

__global__ void k_hist(const int* __restrict__ sl) {
    int i = blockIdx.x * blockDim.x + threadIdx.x;
    if (i < BQ) atomicAdd(&g_hist[sl[i] & 255], 1);
}

__global__ void k_scan() {
    if (threadIdx.x == 0) {
        int s = 0;
        for (int i = 0; i < 256; i++) { int c = g_hist[i]; g_cursor[i] = s; s += c; }
    }
}

__global__ void k_scatter(const int* __restrict__ sl) {
    int i = blockIdx.x * blockDim.x + threadIdx.x;
    if (i < BQ) {
        int pos = atomicAdd(&g_cursor[sl[i] & 255], 1);
        g_perm[pos] = i;
    }
}

// ---------------- math helpers ----------------------------------------------
__device__ __forceinline__ float sigf(float v) {
    return __fdividef(1.f, 1.f + __expf(-v));
}

// ---------------- main AUGRU kernel -----------------------------------------
// One warp owns one row (sequence) at a time, pulled from a descending-L queue.
// SMEM: Wg transposed to [k][lane*4+c] (c in {0,1,2,3} -> output lane+32c),
//       Wc transposed to [k][lane*2+c] (c in {0,1}   -> output lane+32c),
//       per-warp 192-float staging buffer: [0:64)=x_t, [64:128)=h, [128:192)=r*h.
__global__ void __launch_bounds__(256, 1)
augru_main(const float* __restrict__ x, const int* __restrict__ sl,
           const float* __restrict__ att, const float* __restrict__ Wg,
           const float* __restrict__ bg, const float* __restrict__ Wc,
           const float* __restrict__ bc, float* __restrict__ out)
{
    extern __shared__ float sm[];
    float* sWg  = sm;               // 16384 floats
    float* sWc  = sm + 16384;       // 8192 floats
    float* sBg  = sm + 24576;       // 128
    float* sBc  = sm + 24704;       // 64
    float* sBuf = sm + 24768;       // 8 warps * 192

    const int tid = threadIdx.x;

    // cooperative weight load, transposed for per-lane vector LDS
    for (int i = tid; i < 128 * 128; i += 256) {
        int k = i >> 7, j = i & 127;                 // j = lane*4 + c
        sWg[i] = Wg[k * 128 + ((j & 3) << 5) + (j >> 2)];
    }
    for (int i = tid; i < 128 * 64; i += 256) {
        int k = i >> 6, j = i & 63;                  // j = lane*2 + c
        sWc[i] = Wc[k * 64 + ((j & 1) << 5) + (j >> 1)];
    }
    if (tid < 128) sBg[tid] = bg[tid];
    if (tid < 64)  sBc[tid] = bc[tid];
    __syncthreads();

    const int lane = tid & 31;
    float* rb = sBuf + (tid >> 5) * 192;

    const float bgv0 = sBg[lane], bgv1 = sBg[lane + 32];
    const float bgv2 = sBg[lane + 64], bgv3 = sBg[lane + 96];
    const float bcv0 = sBc[lane], bcv1 = sBc[lane + 32];

    for (;;) {
        int ci = 0;
        if (lane == 0) ci = atomicAdd(&g_qhead, 1);
        ci = __shfl_sync(0xffffffffu, ci, 0);
        if (ci >= BQ) break;

        const int row = g_perm[BQ - 1 - ci];         // descending L order
        const int L = sl[row];
        const float* xb = x + (size_t)row * TT * DD;
        const float* ab = att + (size_t)row * TT;
        float* ob = out + (size_t)row * TT * HH;

        float h0 = 0.f, h1 = 0.f;
        rb[64 + lane] = 0.f; rb[96 + lane] = 0.f;

        float px0 = 0.f, px1 = 0.f, pa = 0.f;
        if (L > 0) { px0 = xb[lane]; px1 = xb[lane + 32]; pa = ab[0]; }

        for (int t = 0; t < L; t++) {
            __syncwarp();                            // protect prev-iter reads / h writes
            rb[lane] = px0; rb[32 + lane] = px1;
            const float at_s = pa;
            __syncwarp();                            // x/h visible to all lanes

            // prefetch next timestep while matvecs run
            {
                const int tn = t + 1;
                if (tn < L) {
                    const float* xp = xb + tn * DD;
                    px0 = xp[lane]; px1 = xp[lane + 32]; pa = ab[tn];
                }
            }

            // ---- gate matvec: [x;h](128) @ Wg(128x128) ----
            float a0 = bgv0, a1 = bgv1, a2 = bgv2, a3 = bgv3;
            #pragma unroll 4
            for (int k4 = 0; k4 < 128; k4 += 4) {
                const float4 bv = *(const float4*)(rb + k4);
                const float* wp = sWg + k4 * 128 + lane * 4;
                float4 w0 = *(const float4*)(wp);
                float4 w1 = *(const float4*)(wp + 128);
                float4 w2 = *(const float4*)(wp + 256);
                float4 w3 = *(const float4*)(wp + 384);
                a0 += w0.x * bv.x; a1 += w0.y * bv.x; a2 += w0.z * bv.x; a3 += w0.w * bv.x;
                a0 += w1.x * bv.y; a1 += w1.y * bv.y; a2 += w1.z * bv.y; a3 += w1.w * bv.y;
                a0 += w2.x * bv.z; a1 += w2.y * bv.z; a2 += w2.z * bv.z; a3 += w2.w * bv.z;
                a0 += w3.x * bv.w; a1 += w3.y * bv.w; a2 += w3.z * bv.w; a3 += w3.w * bv.w;
            }
            const float r0 = sigf(a0), r1 = sigf(a1);
            const float u0 = sigf(a2), u1 = sigf(a3);
            rb[128 + lane] = r0 * h0;
            rb[160 + lane] = r1 * h1;
            __syncwarp();                            // r*h visible

            // ---- candidate matvec: [x; r*h](128) @ Wc(128x64) ----
            float c0 = bcv0, c1 = bcv1;
            #pragma unroll 4
            for (int k4 = 0; k4 < 64; k4 += 4) {
                const float4 bv = *(const float4*)(rb + k4);          // x part
                const float* wp = sWc + k4 * 64 + lane * 2;
                float2 w0 = *(const float2*)(wp);
                float2 w1 = *(const float2*)(wp + 64);
                float2 w2 = *(const float2*)(wp + 128);
                float2 w3 = *(const float2*)(wp + 192);
                c0 += w0.x * bv.x; c1 += w0.y * bv.x;
                c0 += w1.x * bv.y; c1 += w1.y * bv.y;
                c0 += w2.x * bv.z; c1 += w2.y * bv.z;
                c0 += w3.x * bv.w; c1 += w3.y * bv.w;
            }
            #pragma unroll 4
            for (int k4 = 0; k4 < 64; k4 += 4) {
                const float4 bv = *(const float4*)(rb + 128 + k4);    // r*h part
                const float* wp = sWc + (64 + k4) * 64 + lane * 2;
                float2 w0 = *(const float2*)(wp);
                float2 w1 = *(const float2*)(wp + 64);
                float2 w2 = *(const float2*)(wp + 128);
                float2 w3 = *(const float2*)(wp + 192);
                c0 += w0.x * bv.x; c1 += w0.y * bv.x;
                c0 += w1.x * bv.y; c1 += w1.y * bv.y;
                c0 += w2.x * bv.z; c1 += w2.y * bv.z;
                c0 += w3.x * bv.w; c1 += w3.y * bv.w;
            }
            const float ct0 = tanhf(c0), ct1 = tanhf(c1);

            const float uu0 = (1.f - at_s) * u0;
            const float uu1 = (1.f - at_s) * u1;
            h0 = uu0 * h0 + (1.f - uu0) * ct0;
            h1 = uu1 * h1 + (1.f - uu1) * ct1;

            float* op = ob + t * HH;
            op[lane] = h0; op[lane + 32] = h1;
            rb[64 + lane] = h0; rb[96 + lane] = h1;  // stage h for next step
        }

        // zero-fill masked tail (output poisoned by harness)
        float* op = ob + L * HH;
        for (int t = L; t < TT; t++) {
            op[lane] = 0.f; op[lane + 32] = 0.f;
            op += HH;
        }
    }
}

// ---------------- launch -----------------------------------------------------
extern "C" void kernel_launch(void* const* d_in, const int* in_sizes, int n_in,
                              void* d_out, int out_size)
{
    const float* x  = (const float*)d_in[0];   // rnn_input  [B,T,64]
    const int*   sl = (const int*)d_in[1];     // sequence_length [B,1]
    const float* at = (const float*)d_in[2];   // att_score  [B,T,1]
    const float* Wg = (const float*)d_in[3];   // [128,128]
    const float* bg = (const float*)d_in[4];   // [128]
    const float* Wc = (const float*)d_in[5];   // [128,64]
    const float* bc = (const float*)d_in[6];   // [64]
    float* out = (float*)d_out;                // [B,T,64]

    const int smem_bytes = (16384 + 8192 + 128 + 64 + 8 * 192) * 4; // 105216
    cudaFuncSetAttribute(augru_main, cudaFuncAttributeMaxDynamicSharedMemorySize,
                         smem_bytes);

    k_hist_init<<<1, 256>>>();
    k_hist<<<(BQ + 255) / 256, 256>>>(sl);
    k_scan<<<1, 32>>>();
    k_scatter<<<(BQ + 255) / 256, 256>>>(sl);
    augru_main<<<148, 256, smem_bytes>>>(x, sl, at, Wg, bg, Wc, bc, out);
}

// round 11
// speedup vs baseline: 1.0014x; 1.0013x over previous
#include <cuda_runtime.h>

#define BQ 4096
#define TT 200
#define DD 64
#define HH 64

// ---------------- scratch (static device globals: allocation-free) ----------
__device__ int g_hist[256];
__device__ int g_cursor[256];
__device__ int g_perm[BQ];
__device__ int g_qhead;

// ---------------- counting sort of rows by seq_len --------------------------
__global__ void k_hist_init() {
    int i = threadIdx.x;
    g_hist[i] = 0;
    if (i == 0) g_qhead = 0;
}

__global__ void k_hist(const int* __restrict__ sl) {
    int i = blockIdx.x * blockDim.x + threadIdx.x;
    if (i < BQ) atomicAdd(&g_hist[sl[i] & 255], 1);
}

__global__ void k_scan() {
    if (threadIdx.x == 0) {
        int s = 0;
        for (int i = 0; i < 256; i++) { int c = g_hist[i]; g_cursor[i] = s; s += c; }
    }
}

__global__ void k_scatter(const int* __restrict__ sl) {
    int i = blockIdx.x * blockDim.x + threadIdx.x;
    if (i < BQ) {
        int pos = atomicAdd(&g_cursor[sl[i] & 255], 1);
        g_perm[pos] = i;
    }
}

// ---------------- math helpers ----------------------------------------------
__device__ __forceinline__ float sigf(float v) {
    return __fdividef(1.f, 1.f + __expf(-v));
}

// ---------------- main AUGRU kernel -----------------------------------------
// One warp owns one row (sequence) at a time, pulled from a descending-L queue.
// SMEM: Wg transposed to [k][lane*4+c] (c in {0,1,2,3} -> output lane+32c),
//       Wc transposed to [k][lane*2+c] (c in {0,1}   -> output lane+32c),
//       per-warp 192-float staging buffer: [0:64)=x_t, [64:128)=h, [128:192)=r*h.
__global__ void __launch_bounds__(256, 1)
augru_main(const float* __restrict__ x, const int* __restrict__ sl,
           const float* __restrict__ att, const float* __restrict__ Wg,
           const float* __restrict__ bg, const float* __restrict__ Wc,
           const float* __restrict__ bc, float* __restrict__ out)
{
    extern __shared__ float sm[];
    float* sWg  = sm;               // 16384 floats
    float* sWc  = sm + 16384;       // 8192 floats
    float* sBg  = sm + 24576;       // 128
    float* sBc  = sm + 24704;       // 64
    float* sBuf = sm + 24768;       // 8 warps * 192

    const int tid = threadIdx.x;

    // cooperative weight load, transposed for per-lane vector LDS
    for (int i = tid; i < 128 * 128; i += 256) {
        int k = i >> 7, j = i & 127;                 // j = lane*4 + c
        sWg[i] = Wg[k * 128 + ((j & 3) << 5) + (j >> 2)];
    }
    for (int i = tid; i < 128 * 64; i += 256) {
        int k = i >> 6, j = i & 63;                  // j = lane*2 + c
        sWc[i] = Wc[k * 64 + ((j & 1) << 5) + (j >> 1)];
    }
    if (tid < 128) sBg[tid] = bg[tid];
    if (tid < 64)  sBc[tid] = bc[tid];
    __syncthreads();

    const int lane = tid & 31;
    float* rb = sBuf + (tid >> 5) * 192;

    const float bgv0 = sBg[lane], bgv1 = sBg[lane + 32];
    const float bgv2 = sBg[lane + 64], bgv3 = sBg[lane + 96];
    const float bcv0 = sBc[lane], bcv1 = sBc[lane + 32];

    for (;;) {
        int ci = 0;
        if (lane == 0) ci = atomicAdd(&g_qhead, 1);
        ci = __shfl_sync(0xffffffffu, ci, 0);
        if (ci >= BQ) break;

        const int row = g_perm[BQ - 1 - ci];         // descending L order
        const int L = sl[row];
        const float* xb = x + (size_t)row * TT * DD;
        const float* ab = att + (size_t)row * TT;
        float* ob = out + (size_t)row * TT * HH;

        float h0 = 0.f, h1 = 0.f;
        rb[64 + lane] = 0.f; rb[96 + lane] = 0.f;

        float px0 = 0.f, px1 = 0.f, pa = 0.f;
        if (L > 0) { px0 = xb[lane]; px1 = xb[lane + 32]; pa = ab[0]; }

        for (int t = 0; t < L; t++) {
            __syncwarp();                            // protect prev-iter reads / h writes
            rb[lane] = px0; rb[32 + lane] = px1;
            const float at_s = pa;
            __syncwarp();                            // x/h visible to all lanes

            // prefetch next timestep while matvecs run
            {
                const int tn = t + 1;
                if (tn < L) {
                    const float* xp = xb + tn * DD;
                    px0 = xp[lane]; px1 = xp[lane + 32]; pa = ab[tn];
                }
            }

            // ---- gate matvec: [x;h](128) @ Wg(128x128) ----
            float a0 = bgv0, a1 = bgv1, a2 = bgv2, a3 = bgv3;
            #pragma unroll 4
            for (int k4 = 0; k4 < 128; k4 += 4) {
                const float4 bv = *(const float4*)(rb + k4);
                const float* wp = sWg + k4 * 128 + lane * 4;
                float4 w0 = *(const float4*)(wp);
                float4 w1 = *(const float4*)(wp + 128);
                float4 w2 = *(const float4*)(wp + 256);
                float4 w3 = *(const float4*)(wp + 384);
                a0 += w0.x * bv.x; a1 += w0.y * bv.x; a2 += w0.z * bv.x; a3 += w0.w * bv.x;
                a0 += w1.x * bv.y; a1 += w1.y * bv.y; a2 += w1.z * bv.y; a3 += w1.w * bv.y;
                a0 += w2.x * bv.z; a1 += w2.y * bv.z; a2 += w2.z * bv.z; a3 += w2.w * bv.z;
                a0 += w3.x * bv.w; a1 += w3.y * bv.w; a2 += w3.z * bv.w; a3 += w3.w * bv.w;
            }
            const float r0 = sigf(a0), r1 = sigf(a1);
            const float u0 = sigf(a2), u1 = sigf(a3);
            rb[128 + lane] = r0 * h0;
            rb[160 + lane] = r1 * h1;
            __syncwarp();                            // r*h visible

            // ---- candidate matvec: [x; r*h](128) @ Wc(128x64) ----
            float c0 = bcv0, c1 = bcv1;
            #pragma unroll 4
            for (int k4 = 0; k4 < 64; k4 += 4) {
                const float4 bv = *(const float4*)(rb + k4);          // x part
                const float* wp = sWc + k4 * 64 + lane * 2;
                float2 w0 = *(const float2*)(wp);
                float2 w1 = *(const float2*)(wp + 64);
                float2 w2 = *(const float2*)(wp + 128);
                float2 w3 = *(const float2*)(wp + 192);
                c0 += w0.x * bv.x; c1 += w0.y * bv.x;
                c0 += w1.x * bv.y; c1 += w1.y * bv.y;
                c0 += w2.x * bv.z; c1 += w2.y * bv.z;
                c0 += w3.x * bv.w; c1 += w3.y * bv.w;
            }
            #pragma unroll 4
            for (int k4 = 0; k4 < 64; k4 += 4) {
                const float4 bv = *(const float4*)(rb + 128 + k4);    // r*h part
                const float* wp = sWc + (64 + k4) * 64 + lane * 2;
                float2 w0 = *(const float2*)(wp);
                float2 w1 = *(const float2*)(wp + 64);
                float2 w2 = *(const float2*)(wp + 128);
                float2 w3 = *(const float2*)(wp + 192);
                c0 += w0.x * bv.x; c1 += w0.y * bv.x;
                c0 += w1.x * bv.y; c1 += w1.y * bv.y;
                c0 += w2.x * bv.z; c1 += w2.y * bv.z;
                c0 += w3.x * bv.w; c1 += w3.y * bv.w;
            }
            const float ct0 = tanhf(c0), ct1 = tanhf(c1);

            const float uu0 = (1.f - at_s) * u0;
            const float uu1 = (1.f - at_s) * u1;
            h0 = uu0 * h0 + (1.f - uu0) * ct0;
            h1 = uu1 * h1 + (1.f - uu1) * ct1;

            float* op = ob + t * HH;
            op[lane] = h0; op[lane + 32] = h1;
            rb[64 + lane] = h0; rb[96 + lane] = h1;  // stage h for next step
        }

        // zero-fill masked tail (output poisoned by harness)
        float* op = ob + L * HH;
        for (int t = L; t < TT; t++) {
            op[lane] = 0.f; op[lane + 32] = 0.f;
            op += HH;
        }
    }
}

// ---------------- launch -----------------------------------------------------
extern "C" void kernel_launch(void* const* d_in, const int* in_sizes, int n_in,
                              void* d_out, int out_size)
{
    const float* x  = (const float*)d_in[0];   // rnn_input  [B,T,64]
    const int*   sl = (const int*)d_in[1];     // sequence_length [B,1]
    const float* at = (const float*)d_in[2];   // att_score  [B,T,1]
    const float* Wg = (const float*)d_in[3];   // [128,128]
    const float* bg = (const float*)d_in[4];   // [128]
    const float* Wc = (const float*)d_in[5];   // [128,64]
    const float* bc = (const float*)d_in[6];   // [64]
    float* out = (float*)d_out;                // [B,T,64]

    const int smem_bytes = (16384 + 8192 + 128 + 64 + 8 * 192) * 4; // 105216
    cudaFuncSetAttribute(augru_main, cudaFuncAttributeMaxDynamicSharedMemorySize,
                         smem_bytes);

    k_hist_init<<<1, 256>>>();
    k_hist<<<(BQ + 255) / 256, 256>>>(sl);
    k_scan<<<1, 32>>>();
    k_scatter<<<(BQ + 255) / 256, 256>>>(sl);
    augru_main<<<148, 256, smem_bytes>>>(x, sl, at, Wg, bg, Wc, bc, out);
}

// round 12
// speedup vs baseline: 1.0016x; 1.0002x over previous
#include <cuda_runtime.h>

#define BQ 4096
#define TT 200
#define DD 64
#define HH 64

// ---------------- scratch (static device globals: allocation-free) ----------
__device__ int g_hist[256];
__device__ int g_cursor[256];
__device__ int g_perm[BQ];
__device__ int g_qhead;

// ---------------- counting sort of rows by seq_len --------------------------
__global__ void k_hist_init() {
    int i = threadIdx.x;
    g_hist[i] = 0;
    if (i == 0) g_qhead = 0;
}

__global__ void k_hist(const int* __restrict__ sl) {
    int i = blockIdx.x * blockDim.x + threadIdx.x;
    if (i < BQ) atomicAdd(&g_hist[sl[i] & 255], 1);
}

__global__ void k_scan() {
    if (threadIdx.x == 0) {
        int s = 0;
        for (int i = 0; i < 256; i++) { int c = g_hist[i]; g_cursor[i] = s; s += c; }
    }
}

__global__ void k_scatter(const int* __restrict__ sl) {
    int i = blockIdx.x * blockDim.x + threadIdx.x;
    if (i < BQ) {
        int pos = atomicAdd(&g_cursor[sl[i] & 255], 1);
        g_perm[pos] = i;
    }
}

// ---------------- math helpers ----------------------------------------------
__device__ __forceinline__ float sigf(float v) {
    return __fdividef(1.f, 1.f + __expf(-v));
}

// ---------------- main AUGRU kernel -----------------------------------------
// One warp owns one row (sequence) at a time, pulled from a descending-L queue.
// SMEM: Wg transposed to [k][lane*4+c] (c in {0,1,2,3} -> output lane+32c),
//       Wc transposed to [k][lane*2+c] (c in {0,1}   -> output lane+32c),
//       per-warp 192-float staging buffer: [0:64)=x_t, [64:128)=h, [128:192)=r*h.
__global__ void __launch_bounds__(256, 1)
augru_main(const float* __restrict__ x, const int* __restrict__ sl,
           const float* __restrict__ att, const float* __restrict__ Wg,
           const float* __restrict__ bg, const float* __restrict__ Wc,
           const float* __restrict__ bc, float* __restrict__ out)
{
    extern __shared__ float sm[];
    float* sWg  = sm;               // 16384 floats
    float* sWc  = sm + 16384;       // 8192 floats
    float* sBg  = sm + 24576;       // 128
    float* sBc  = sm + 24704;       // 64
    float* sBuf = sm + 24768;       // 8 warps * 192

    const int tid = threadIdx.x;

    // cooperative weight load, transposed for per-lane vector LDS
    for (int i = tid; i < 128 * 128; i += 256) {
        int k = i >> 7, j = i & 127;                 // j = lane*4 + c
        sWg[i] = Wg[k * 128 + ((j & 3) << 5) + (j >> 2)];
    }
    for (int i = tid; i < 128 * 64; i += 256) {
        int k = i >> 6, j = i & 63;                  // j = lane*2 + c
        sWc[i] = Wc[k * 64 + ((j & 1) << 5) + (j >> 1)];
    }
    if (tid < 128) sBg[tid] = bg[tid];
    if (tid < 64)  sBc[tid] = bc[tid];
    __syncthreads();

    const int lane = tid & 31;
    float* rb = sBuf + (tid >> 5) * 192;

    const float bgv0 = sBg[lane], bgv1 = sBg[lane + 32];
    const float bgv2 = sBg[lane + 64], bgv3 = sBg[lane + 96];
    const float bcv0 = sBc[lane], bcv1 = sBc[lane + 32];

    for (;;) {
        int ci = 0;
        if (lane == 0) ci = atomicAdd(&g_qhead, 1);
        ci = __shfl_sync(0xffffffffu, ci, 0);
        if (ci >= BQ) break;

        const int row = g_perm[BQ - 1 - ci];         // descending L order
        const int L = sl[row];
        const float* xb = x + (size_t)row * TT * DD;
        const float* ab = att + (size_t)row * TT;
        float* ob = out + (size_t)row * TT * HH;

        float h0 = 0.f, h1 = 0.f;
        rb[64 + lane] = 0.f; rb[96 + lane] = 0.f;

        float px0 = 0.f, px1 = 0.f, pa = 0.f;
        if (L > 0) { px0 = xb[lane]; px1 = xb[lane + 32]; pa = ab[0]; }

        for (int t = 0; t < L; t++) {
            __syncwarp();                            // protect prev-iter reads / h writes
            rb[lane] = px0; rb[32 + lane] = px1;
            const float at_s = pa;
            __syncwarp();                            // x/h visible to all lanes

            // prefetch next timestep while matvecs run
            {
                const int tn = t + 1;
                if (tn < L) {
                    const float* xp = xb + tn * DD;
                    px0 = xp[lane]; px1 = xp[lane + 32]; pa = ab[tn];
                }
            }

            // ---- gate matvec: [x;h](128) @ Wg(128x128) ----
            float a0 = bgv0, a1 = bgv1, a2 = bgv2, a3 = bgv3;
            #pragma unroll 4
            for (int k4 = 0; k4 < 128; k4 += 4) {
                const float4 bv = *(const float4*)(rb + k4);
                const float* wp = sWg + k4 * 128 + lane * 4;
                float4 w0 = *(const float4*)(wp);
                float4 w1 = *(const float4*)(wp + 128);
                float4 w2 = *(const float4*)(wp + 256);
                float4 w3 = *(const float4*)(wp + 384);
                a0 += w0.x * bv.x; a1 += w0.y * bv.x; a2 += w0.z * bv.x; a3 += w0.w * bv.x;
                a0 += w1.x * bv.y; a1 += w1.y * bv.y; a2 += w1.z * bv.y; a3 += w1.w * bv.y;
                a0 += w2.x * bv.z; a1 += w2.y * bv.z; a2 += w2.z * bv.z; a3 += w2.w * bv.z;
                a0 += w3.x * bv.w; a1 += w3.y * bv.w; a2 += w3.z * bv.w; a3 += w3.w * bv.w;
            }
            const float r0 = sigf(a0), r1 = sigf(a1);
            const float u0 = sigf(a2), u1 = sigf(a3);
            rb[128 + lane] = r0 * h0;
            rb[160 + lane] = r1 * h1;
            __syncwarp();                            // r*h visible

            // ---- candidate matvec: [x; r*h](128) @ Wc(128x64) ----
            float c0 = bcv0, c1 = bcv1;
            #pragma unroll 4
            for (int k4 = 0; k4 < 64; k4 += 4) {
                const float4 bv = *(const float4*)(rb + k4);          // x part
                const float* wp = sWc + k4 * 64 + lane * 2;
                float2 w0 = *(const float2*)(wp);
                float2 w1 = *(const float2*)(wp + 64);
                float2 w2 = *(const float2*)(wp + 128);
                float2 w3 = *(const float2*)(wp + 192);
                c0 += w0.x * bv.x; c1 += w0.y * bv.x;
                c0 += w1.x * bv.y; c1 += w1.y * bv.y;
                c0 += w2.x * bv.z; c1 += w2.y * bv.z;
                c0 += w3.x * bv.w; c1 += w3.y * bv.w;
            }
            #pragma unroll 4
            for (int k4 = 0; k4 < 64; k4 += 4) {
                const float4 bv = *(const float4*)(rb + 128 + k4);    // r*h part
                const float* wp = sWc + (64 + k4) * 64 + lane * 2;
                float2 w0 = *(const float2*)(wp);
                float2 w1 = *(const float2*)(wp + 64);
                float2 w2 = *(const float2*)(wp + 128);
                float2 w3 = *(const float2*)(wp + 192);
                c0 += w0.x * bv.x; c1 += w0.y * bv.x;
                c0 += w1.x * bv.y; c1 += w1.y * bv.y;
                c0 += w2.x * bv.z; c1 += w2.y * bv.z;
                c0 += w3.x * bv.w; c1 += w3.y * bv.w;
            }
            const float ct0 = tanhf(c0), ct1 = tanhf(c1);

            const float uu0 = (1.f - at_s) * u0;
            const float uu1 = (1.f - at_s) * u1;
            h0 = uu0 * h0 + (1.f - uu0) * ct0;
            h1 = uu1 * h1 + (1.f - uu1) * ct1;

            float* op = ob + t * HH;
            op[lane] = h0; op[lane + 32] = h1;
            rb[64 + lane] = h0; rb[96 + lane] = h1;  // stage h for next step
        }

        // zero-fill masked tail (output poisoned by harness)
        float* op = ob + L * HH;
        for (int t = L; t < TT; t++) {
            op[lane] = 0.f; op[lane + 32] = 0.f;
            op += HH;
        }
    }
}

// ---------------- launch -----------------------------------------------------
extern "C" void kernel_launch(void* const* d_in, const int* in_sizes, int n_in,
                              void* d_out, int out_size)
{
    const float* x  = (const float*)d_in[0];   // rnn_input  [B,T,64]
    const int*   sl = (const int*)d_in[1];     // sequence_length [B,1]
    const float* at = (const float*)d_in[2];   // att_score  [B,T,1]
    const float* Wg = (const float*)d_in[3];   // [128,128]
    const float* bg = (const float*)d_in[4];   // [128]
    const float* Wc = (const float*)d_in[5];   // [128,64]
    const float* bc = (const float*)d_in[6];   // [64]
    float* out = (float*)d_out;                // [B,T,64]

    const int smem_bytes = (16384 + 8192 + 128 + 64 + 8 * 192) * 4; // 105216
    cudaFuncSetAttribute(augru_main, cudaFuncAttributeMaxDynamicSharedMemorySize,
                         smem_bytes);

    k_hist_init<<<1, 256>>>();
    k_hist<<<(BQ + 255) / 256, 256>>>(sl);
    k_scan<<<1, 32>>>();
    k_scatter<<<(BQ + 255) / 256, 256>>>(sl);
    augru_main<<<148, 256, smem_bytes>>>(x, sl, at, Wg, bg, Wc, bc, out);
}